// round 2
// baseline (speedup 1.0000x reference)
#include <cuda_runtime.h>
#include <math.h>

#define NN 32768
#define GG 512
#define MAXNODE 64
#define EE 262144

// ---------------- scratch (static device globals; no allocation) ----------------
__device__ float g_tv[GG * 256];          // [ve | te] per graph
__device__ float g_start[GG * 128];
__device__ float g_embproj[51 * 128];
__device__ float g_x0[NN * 128];          // layernormed node features
__device__ float g_xp1[NN * 512];         // x0 @ W1
__device__ float g_x1[NN * 512];          // conv1 output (post elu)
__device__ float g_als1[NN * 4];
__device__ float g_ald1[NN * 4];
__device__ float g_xp2[NN * 128];         // x1 @ W2
__device__ float g_x2[NN * 128];          // conv2 output
__device__ float g_als2[NN];
__device__ float g_ald2[NN];
__device__ int   g_cnt[NN];
__device__ int   g_rowptr[NN + 1];
__device__ int   g_cursor[NN];
__device__ int   g_sorted[EE];            // src sorted by dst
__device__ float g_pooled[GG * 128];

// ---------------- helpers ----------------
__device__ __forceinline__ float warp_sum(float v) {
#pragma unroll
    for (int o = 16; o > 0; o >>= 1) v += __shfl_xor_sync(0xffffffffu, v, o);
    return v;
}
__device__ __forceinline__ float warp_max(float v) {
#pragma unroll
    for (int o = 16; o > 0; o >>= 1) v = fmaxf(v, __shfl_xor_sync(0xffffffffu, v, o));
    return v;
}
__device__ __forceinline__ float lrelu02(float x) { return x > 0.f ? x : 0.2f * x; }
__device__ __forceinline__ float elu1(float x) { return x > 0.f ? x : (expf(x) - 1.f); }

// ---------------- stage 1: graph-level embeds ----------------
// tv[g][0:128] = v[g]@Wv+bv ; tv[g][128:256] = t[g]@Wt+bt. 4 graphs/block.
__global__ void k_tv(const float* __restrict__ t, const float* __restrict__ v,
                     const float* __restrict__ Wt, const float* __restrict__ bt,
                     const float* __restrict__ Wv, const float* __restrict__ bv) {
    const int GT = 4;
    __shared__ float sv[GT][768];
    __shared__ float st[GT][768];
    int g0 = blockIdx.x * GT;
    for (int i = threadIdx.x; i < GT * 768; i += 256) {
        int gi = i / 768, k = i - gi * 768;
        sv[gi][k] = v[(g0 + gi) * 768 + k];
        st[gi][k] = t[(g0 + gi) * 768 + k];
    }
    __syncthreads();
    int j = threadIdx.x;          // 0..255
    int col = j & 127;
    bool isv = (j < 128);
    const float* W = isv ? Wv : Wt;
    float (*S)[768] = isv ? sv : st;
    float acc[GT] = {0.f, 0.f, 0.f, 0.f};
    for (int k = 0; k < 768; k++) {
        float w = W[k * 128 + col];
#pragma unroll
        for (int gi = 0; gi < GT; gi++) acc[gi] += S[gi][k] * w;
    }
    float b = isv ? bv[col] : bt[col];
#pragma unroll
    for (int gi = 0; gi < GT; gi++) g_tv[(g0 + gi) * 256 + j] = acc[gi] + b;
}

// start[g] = tv[g] @ Wstart + bstart   (256 -> 128). 4 graphs/block, 128 thr.
__global__ void k_start(const float* __restrict__ Ws, const float* __restrict__ bs) {
    const int GT = 4;
    __shared__ float s[GT][256];
    int g0 = blockIdx.x * GT;
    for (int i = threadIdx.x; i < GT * 256; i += 128) ((float*)s)[i] = g_tv[g0 * 256 + i];
    __syncthreads();
    int j = threadIdx.x;
    float acc[GT] = {0.f, 0.f, 0.f, 0.f};
    for (int k = 0; k < 256; k++) {
        float w = Ws[k * 128 + j];
#pragma unroll
        for (int gi = 0; gi < GT; gi++) acc[gi] += s[gi][k] * w;
    }
    float b = bs[j];
#pragma unroll
    for (int gi = 0; gi < GT; gi++) g_start[(g0 + gi) * 128 + j] = acc[gi] + b;
}

// emb_proj = emb @ Wnode + bnode   (51x128). One block per row.
__global__ void k_embproj(const float* __restrict__ emb, const float* __restrict__ Wn,
                          const float* __restrict__ bn) {
    __shared__ float se[128];
    int j = threadIdx.x;
    se[j] = emb[blockIdx.x * 128 + j];
    __syncthreads();
    float acc = 0.f;
    for (int k = 0; k < 128; k++) acc += se[k] * Wn[k * 128 + j];
    g_embproj[blockIdx.x * 128 + j] = acc + bn[j];
}

// gather row (start for local node 0, emb_proj otherwise) + layernorm. 1 warp/node.
__global__ void k_build(const int* __restrict__ m_idx, const float* __restrict__ lg,
                        const float* __restrict__ lb) {
    int w = (blockIdx.x * blockDim.x + threadIdx.x) >> 5;
    int lane = threadIdx.x & 31;
    if (w >= NN) return;
    int local = w & 63, g = w >> 6;
    const float* src = (local == 0) ? (g_start + g * 128) : (g_embproj + m_idx[w] * 128);
    float4 x = *(const float4*)(src + lane * 4);
    float mu = warp_sum(x.x + x.y + x.z + x.w) * (1.f / 128.f);
    float dx = x.x - mu, dy = x.y - mu, dz = x.z - mu, dw = x.w - mu;
    float var = warp_sum(dx * dx + dy * dy + dz * dz + dw * dw) * (1.f / 128.f);
    float inv = rsqrtf(var + 1e-6f);
    float4 gv = *(const float4*)(lg + lane * 4);
    float4 bv = *(const float4*)(lb + lane * 4);
    float4 o;
    o.x = dx * inv * gv.x + bv.x;
    o.y = dy * inv * gv.y + bv.y;
    o.z = dz * inv * gv.z + bv.z;
    o.w = dw * inv * gv.w + bv.w;
    *(float4*)(g_x0 + w * 128 + lane * 4) = o;
}

// ---------------- edge CSR (counting sort by dst) ----------------
__global__ void k_zero() {
    int i = blockIdx.x * blockDim.x + threadIdx.x;
    if (i < NN) g_cnt[i] = 0;
}
__global__ void k_hist(const int* __restrict__ dst) {
    int e = blockIdx.x * blockDim.x + threadIdx.x;
    if (e < EE) atomicAdd(&g_cnt[dst[e]], 1);
}
__global__ void k_scan() {    // single block, 1024 threads, 32 elems each
    __shared__ int ss[1024];
    int t = threadIdx.x;
    int base = t * 32;
    int c[32];
    int s = 0;
#pragma unroll
    for (int i = 0; i < 32; i++) { c[i] = g_cnt[base + i]; s += c[i]; }
    ss[t] = s;
    __syncthreads();
    for (int off = 1; off < 1024; off <<= 1) {
        int v = (t >= off) ? ss[t - off] : 0;
        __syncthreads();
        ss[t] += v;
        __syncthreads();
    }
    int run = ss[t] - s;
#pragma unroll
    for (int i = 0; i < 32; i++) {
        g_rowptr[base + i] = run;
        g_cursor[base + i] = run;
        run += c[i];
    }
    if (t == 1023) g_rowptr[NN] = run;
}
__global__ void k_scatter(const int* __restrict__ src, const int* __restrict__ dst) {
    int e = blockIdx.x * blockDim.x + threadIdx.x;
    if (e < EE) {
        int p = atomicAdd(&g_cursor[dst[e]], 1);
        g_sorted[p] = src[e];
    }
}

// ---------------- fp32 tiled GEMM: C[NN,N] = A[NN,K] @ B[K,N] ----------------
__global__ void k_gemm(const float* __restrict__ A, const float* __restrict__ B,
                       float* __restrict__ C, int N, int K) {
    __shared__ float As[16][64];
    __shared__ float Bs[16][64];
    int bm = blockIdx.y * 64, bn = blockIdx.x * 64;
    int tid = threadIdx.x;
    int tx = tid & 15, ty = tid >> 4;
    float acc[4][4] = {};
    for (int k0 = 0; k0 < K; k0 += 16) {
        int r = tid >> 2, c4 = (tid & 3) << 2;
        float4 av = *(const float4*)&A[(bm + r) * K + k0 + c4];
        As[c4 + 0][r] = av.x; As[c4 + 1][r] = av.y;
        As[c4 + 2][r] = av.z; As[c4 + 3][r] = av.w;
        int br = tid >> 4, bc = (tid & 15) << 2;
        *(float4*)&Bs[br][bc] = *(const float4*)&B[(k0 + br) * N + bn + bc];
        __syncthreads();
#pragma unroll
        for (int kk = 0; kk < 16; kk++) {
            float4 a = *(const float4*)&As[kk][ty << 2];
            float4 b = *(const float4*)&Bs[kk][tx << 2];
            acc[0][0] += a.x * b.x; acc[0][1] += a.x * b.y; acc[0][2] += a.x * b.z; acc[0][3] += a.x * b.w;
            acc[1][0] += a.y * b.x; acc[1][1] += a.y * b.y; acc[1][2] += a.y * b.z; acc[1][3] += a.y * b.w;
            acc[2][0] += a.z * b.x; acc[2][1] += a.z * b.y; acc[2][2] += a.z * b.z; acc[2][3] += a.z * b.w;
            acc[3][0] += a.w * b.x; acc[3][1] += a.w * b.y; acc[3][2] += a.w * b.z; acc[3][3] += a.w * b.w;
        }
        __syncthreads();
    }
#pragma unroll
    for (int i = 0; i < 4; i++) {
        float4 o = make_float4(acc[i][0], acc[i][1], acc[i][2], acc[i][3]);
        *(float4*)&C[(bm + (ty << 2) + i) * N + bn + (tx << 2)] = o;
    }
}

// ---------------- attention coefficients: als/ald = <xp[n,h,:], a_{src,dst}[h]> ----------------
template <int HEADS>
__global__ void k_attn(const float* __restrict__ xp, const float* __restrict__ asrc,
                       const float* __restrict__ adst, float* __restrict__ als,
                       float* __restrict__ ald) {
    int gw = (blockIdx.x * blockDim.x + threadIdx.x) >> 5;   // node*HEADS + h
    int lane = threadIdx.x & 31;
    if (gw >= NN * HEADS) return;
    int h = gw % HEADS;
    const float* row = xp + gw * 128;
    float4 x = *(const float4*)(row + lane * 4);
    float4 a = *(const float4*)(asrc + h * 128 + lane * 4);
    float4 b = *(const float4*)(adst + h * 128 + lane * 4);
    float ps = warp_sum(x.x * a.x + x.y * a.y + x.z * a.z + x.w * a.w);
    float pd = warp_sum(x.x * b.x + x.y * b.y + x.z * b.z + x.w * b.w);
    if (lane == 0) { als[gw] = ps; ald[gw] = pd; }
}

// ---------------- segment softmax + aggregation + bias + elu. 1 warp/dst node ----------------
template <int HEADS>
__global__ void k_agg(const float* __restrict__ xp, const float* __restrict__ als,
                      const float* __restrict__ ald, const float* __restrict__ bias,
                      float* __restrict__ out) {
    int d = (blockIdx.x * blockDim.x + threadIdx.x) >> 5;
    int lane = threadIdx.x & 31;
    if (d >= NN) return;
    int r0 = g_rowptr[d], r1 = g_rowptr[d + 1];
    float aldd[HEADS], alsd[HEADS];
#pragma unroll
    for (int h = 0; h < HEADS; h++) {
        aldd[h] = ald[d * HEADS + h];
        alsd[h] = als[d * HEADS + h];
    }
    // pass 1: segment max (incl. self loop)
    float m[HEADS];
#pragma unroll
    for (int h = 0; h < HEADS; h++) m[h] = lrelu02(alsd[h] + aldd[h]);
    for (int e = r0 + lane; e < r1; e += 32) {
        int s = g_sorted[e];
#pragma unroll
        for (int h = 0; h < HEADS; h++)
            m[h] = fmaxf(m[h], lrelu02(als[s * HEADS + h] + aldd[h]));
    }
#pragma unroll
    for (int h = 0; h < HEADS; h++) m[h] = warp_max(m[h]);

    // pass 2: denom + weighted message sum
    float denom[HEADS];
    float acc[HEADS * 4];
#pragma unroll
    for (int i = 0; i < HEADS * 4; i++) acc[i] = 0.f;
    {   // self loop
        float w[HEADS];
#pragma unroll
        for (int h = 0; h < HEADS; h++) {
            w[h] = expf(lrelu02(alsd[h] + aldd[h]) - m[h]);
            denom[h] = w[h];
        }
        const float* rowp = xp + d * HEADS * 128;
#pragma unroll
        for (int h = 0; h < HEADS; h++) {
            float4 xv = *(const float4*)(rowp + h * 128 + lane * 4);
            acc[h * 4 + 0] += w[h] * xv.x; acc[h * 4 + 1] += w[h] * xv.y;
            acc[h * 4 + 2] += w[h] * xv.z; acc[h * 4 + 3] += w[h] * xv.w;
        }
    }
    for (int e = r0; e < r1; e++) {
        int s = g_sorted[e];   // warp-uniform
        float w[HEADS];
#pragma unroll
        for (int h = 0; h < HEADS; h++) {
            w[h] = expf(lrelu02(als[s * HEADS + h] + aldd[h]) - m[h]);
            denom[h] += w[h];
        }
        const float* rowp = xp + s * HEADS * 128;
#pragma unroll
        for (int h = 0; h < HEADS; h++) {
            float4 xv = *(const float4*)(rowp + h * 128 + lane * 4);
            acc[h * 4 + 0] += w[h] * xv.x; acc[h * 4 + 1] += w[h] * xv.y;
            acc[h * 4 + 2] += w[h] * xv.z; acc[h * 4 + 3] += w[h] * xv.w;
        }
    }
#pragma unroll
    for (int h = 0; h < HEADS; h++) {
        float inv = 1.f / denom[h];
        float4 bv = *(const float4*)(bias + h * 128 + lane * 4);
        float4 o;
        o.x = elu1(acc[h * 4 + 0] * inv + bv.x);
        o.y = elu1(acc[h * 4 + 1] * inv + bv.y);
        o.z = elu1(acc[h * 4 + 2] * inv + bv.z);
        o.w = elu1(acc[h * 4 + 3] * inv + bv.w);
        *(float4*)(out + d * HEADS * 128 + h * 128 + lane * 4) = o;
    }
}

// ---------------- masked mean pooling ----------------
__global__ void k_pool(const int* __restrict__ m_idx) {
    int g = blockIdx.x, j = threadIdx.x;   // 128 threads
    float s = 0.f;
    int cnt = 0;
    for (int n = 0; n < MAXNODE; n++) {
        int node = g * MAXNODE + n;
        if (m_idx[node] >= 1) { s += g_x2[node * 128 + j]; cnt++; }
    }
    g_pooled[g * 128 + j] = s / (float)cnt;
}

// ---------------- output head: leaky_relu(pooled@Wo1+bo1, .01) @ Wo2 + bo2 ----------------
__global__ void k_head(const float* __restrict__ Wo1, const float* __restrict__ bo1,
                       const float* __restrict__ Wo2, const float* __restrict__ bo2,
                       float* __restrict__ out) {
    int g = blockIdx.x, j = threadIdx.x;   // 128 threads
    __shared__ float sp[128];
    __shared__ float red[128];
    sp[j] = g_pooled[g * 128 + j];
    __syncthreads();
    float acc = 0.f;
    for (int k = 0; k < 128; k++) acc += sp[k] * Wo1[k * 128 + j];
    acc += bo1[j];
    float h1 = acc > 0.f ? acc : 0.01f * acc;
    red[j] = h1 * Wo2[j];
    __syncthreads();
    for (int off = 64; off > 0; off >>= 1) {
        if (j < off) red[j] += red[j + off];
        __syncthreads();
    }
    if (j == 0) out[g] = red[0] + bo2[0];
}

// ---------------- host ----------------
extern "C" void kernel_launch(void* const* d_in, const int* in_sizes, int n_in,
                              void* d_out, int out_size) {
    int it, iv, im, iei, iWt, ibt, iWv, ibv, iemb, iWn, ibn, iWs, ibs, ilg, ilb;
    int iW1, ias1, iad1, ib1, iW2, ias2, iad2, ib2, iWo1, ibo1, iWo2, ibo2;
    if (in_sizes[2] == NN) {   // setup_inputs dict order
        it = 0; iv = 1; im = 2; iei = 3; iWt = 4; ibt = 5; iWv = 6; ibv = 7;
        iemb = 8; iWn = 9; ibn = 10; iWs = 11; ibs = 12; ilg = 13; ilb = 14;
        iW1 = 15; ias1 = 16; iad1 = 17; ib1 = 18; iW2 = 19; ias2 = 20; iad2 = 21;
        ib2 = 22; iWo1 = 23; ibo1 = 24; iWo2 = 25; ibo2 = 26;
    } else {                   // reference() signature order
        it = 0; iv = 1; iWt = 2; ibt = 3; iWv = 4; ibv = 5; iemb = 6; iWn = 7;
        ibn = 8; iWs = 9; ibs = 10; ilg = 11; ilb = 12; iW1 = 13; ias1 = 14;
        iad1 = 15; ib1 = 16; iW2 = 17; ias2 = 18; iad2 = 19; ib2 = 20;
        iWo1 = 21; ibo1 = 22; iWo2 = 23; ibo2 = 24; im = 25; iei = 26;
    }
    const float* t   = (const float*)d_in[it];
    const float* v   = (const float*)d_in[iv];
    const int*   mi  = (const int*)d_in[im];
    const int*   ei  = (const int*)d_in[iei];
    const float* Wt  = (const float*)d_in[iWt];
    const float* bt  = (const float*)d_in[ibt];
    const float* Wv  = (const float*)d_in[iWv];
    const float* bv  = (const float*)d_in[ibv];
    const float* emb = (const float*)d_in[iemb];
    const float* Wn  = (const float*)d_in[iWn];
    const float* bn  = (const float*)d_in[ibn];
    const float* Ws  = (const float*)d_in[iWs];
    const float* bs  = (const float*)d_in[ibs];
    const float* lg  = (const float*)d_in[ilg];
    const float* lb  = (const float*)d_in[ilb];
    const float* W1  = (const float*)d_in[iW1];
    const float* as1 = (const float*)d_in[ias1];
    const float* ad1 = (const float*)d_in[iad1];
    const float* b1  = (const float*)d_in[ib1];
    const float* W2  = (const float*)d_in[iW2];
    const float* as2 = (const float*)d_in[ias2];
    const float* ad2 = (const float*)d_in[iad2];
    const float* b2  = (const float*)d_in[ib2];
    const float* Wo1 = (const float*)d_in[iWo1];
    const float* bo1 = (const float*)d_in[ibo1];
    const float* Wo2 = (const float*)d_in[iWo2];
    const float* bo2 = (const float*)d_in[ibo2];
    const int* esrc = ei;
    const int* edst = ei + EE;

    float *p_x0, *p_xp1, *p_x1, *p_als1, *p_ald1, *p_xp2, *p_x2, *p_als2, *p_ald2;
    cudaGetSymbolAddress((void**)&p_x0, g_x0);
    cudaGetSymbolAddress((void**)&p_xp1, g_xp1);
    cudaGetSymbolAddress((void**)&p_x1, g_x1);
    cudaGetSymbolAddress((void**)&p_als1, g_als1);
    cudaGetSymbolAddress((void**)&p_ald1, g_ald1);
    cudaGetSymbolAddress((void**)&p_xp2, g_xp2);
    cudaGetSymbolAddress((void**)&p_x2, g_x2);
    cudaGetSymbolAddress((void**)&p_als2, g_als2);
    cudaGetSymbolAddress((void**)&p_ald2, g_ald2);

    // stage 1: embeds + layernorm
    k_tv<<<GG / 4, 256>>>(t, v, Wt, bt, Wv, bv);
    k_start<<<GG / 4, 128>>>(Ws, bs);
    k_embproj<<<51, 128>>>(emb, Wn, bn);
    k_build<<<NN / 8, 256>>>(mi, lg, lb);

    // edge CSR (independent of features)
    k_zero<<<NN / 256, 256>>>();
    k_hist<<<EE / 256, 256>>>(edst);
    k_scan<<<1, 1024>>>();
    k_scatter<<<EE / 256, 256>>>(esrc, edst);

    // conv1: xp1 = x0 @ W1 (K=128, N=512)
    k_gemm<<<dim3(8, 512), 256>>>(p_x0, W1, p_xp1, 512, 128);
    k_attn<4><<<(NN * 4 * 32) / 256, 256>>>(p_xp1, as1, ad1, p_als1, p_ald1);
    k_agg<4><<<(NN * 32) / 256, 256>>>(p_xp1, p_als1, p_ald1, b1, p_x1);

    // conv2: xp2 = x1 @ W2 (K=512, N=128)
    k_gemm<<<dim3(2, 512), 256>>>(p_x1, W2, p_xp2, 128, 512);
    k_attn<1><<<(NN * 32) / 256, 256>>>(p_xp2, as2, ad2, p_als2, p_ald2);
    k_agg<1><<<(NN * 32) / 256, 256>>>(p_xp2, p_als2, p_ald2, b2, p_x2);

    // pool + head
    k_pool<<<GG, 128>>>(mi);
    k_head<<<GG, 128>>>(Wo1, bo1, Wo2, bo2, (float*)d_out);
}

// round 5
// speedup vs baseline: 1.2972x; 1.2972x over previous
#include <cuda_runtime.h>
#include <math.h>

#define NN 32768
#define GG 512
#define MAXNODE 64
#define EE 262144
#define NROW 563            // 51 type rows + 512 start rows
#define NROWP 576           // padded to 64 multiple for GEMM tiles

// ---------------- scratch (static device globals; no allocation) ----------------
__device__ float g_tv[GG * 256];          // [ve | te] per graph
__device__ float g_start[GG * 128];
__device__ float g_embproj[51 * 128];
__device__ float g_x0t[NROWP * 128];      // layernormed distinct rows (table)
__device__ float g_xp1t[NROWP * 512];     // x0_table @ W1
__device__ float g_x1[NN * 512];          // conv1 output (post elu, per node)
__device__ float g_als1[NROWP * 4];
__device__ float g_ald1[NROWP * 4];
__device__ float g_xp2[NN * 128];         // x1 @ W2
__device__ float g_x2[NN * 128];          // conv2 output
__device__ float g_als2[NN];
__device__ float g_ald2[NN];
__device__ int   g_rid[NN];               // node -> distinct row id
__device__ int   g_cnt[NN];
__device__ int   g_rowptr[NN + 1];
__device__ int   g_cursor[NN];
__device__ int   g_sorted[EE];            // src sorted by dst
__device__ float g_pooled[GG * 128];

// ---------------- helpers ----------------
__device__ __forceinline__ float warp_sum(float v) {
#pragma unroll
    for (int o = 16; o > 0; o >>= 1) v += __shfl_xor_sync(0xffffffffu, v, o);
    return v;
}
__device__ __forceinline__ float warp_max(float v) {
#pragma unroll
    for (int o = 16; o > 0; o >>= 1) v = fmaxf(v, __shfl_xor_sync(0xffffffffu, v, o));
    return v;
}
__device__ __forceinline__ float lrelu02(float x) { return x > 0.f ? x : 0.2f * x; }
__device__ __forceinline__ float elu1(float x) { return x > 0.f ? x : (expf(x) - 1.f); }

// ---------------- stage 1: graph-level embeds ----------------
__global__ void k_tv(const float* __restrict__ t, const float* __restrict__ v,
                     const float* __restrict__ Wt, const float* __restrict__ bt,
                     const float* __restrict__ Wv, const float* __restrict__ bv) {
    const int GT = 4;
    __shared__ float sv[GT][768];
    __shared__ float st[GT][768];
    int g0 = blockIdx.x * GT;
    for (int i = threadIdx.x; i < GT * 768; i += 256) {
        int gi = i / 768, k = i - gi * 768;
        sv[gi][k] = v[(g0 + gi) * 768 + k];
        st[gi][k] = t[(g0 + gi) * 768 + k];
    }
    __syncthreads();
    int j = threadIdx.x;
    int col = j & 127;
    bool isv = (j < 128);
    const float* W = isv ? Wv : Wt;
    float (*S)[768] = isv ? sv : st;
    float acc[GT] = {0.f, 0.f, 0.f, 0.f};
    for (int k = 0; k < 768; k++) {
        float w = W[k * 128 + col];
#pragma unroll
        for (int gi = 0; gi < GT; gi++) acc[gi] += S[gi][k] * w;
    }
    float b = isv ? bv[col] : bt[col];
#pragma unroll
    for (int gi = 0; gi < GT; gi++) g_tv[(g0 + gi) * 256 + j] = acc[gi] + b;
}

__global__ void k_start(const float* __restrict__ Ws, const float* __restrict__ bs) {
    const int GT = 4;
    __shared__ float s[GT][256];
    int g0 = blockIdx.x * GT;
    for (int i = threadIdx.x; i < GT * 256; i += 128) ((float*)s)[i] = g_tv[g0 * 256 + i];
    __syncthreads();
    int j = threadIdx.x;
    float acc[GT] = {0.f, 0.f, 0.f, 0.f};
    for (int k = 0; k < 256; k++) {
        float w = Ws[k * 128 + j];
#pragma unroll
        for (int gi = 0; gi < GT; gi++) acc[gi] += s[gi][k] * w;
    }
    float b = bs[j];
#pragma unroll
    for (int gi = 0; gi < GT; gi++) g_start[(g0 + gi) * 128 + j] = acc[gi] + b;
}

__global__ void k_embproj(const float* __restrict__ emb, const float* __restrict__ Wn,
                          const float* __restrict__ bn) {
    __shared__ float se[128];
    int j = threadIdx.x;
    se[j] = emb[blockIdx.x * 128 + j];
    __syncthreads();
    float acc = 0.f;
    for (int k = 0; k < 128; k++) acc += se[k] * Wn[k * 128 + j];
    g_embproj[blockIdx.x * 128 + j] = acc + bn[j];
}

// build distinct-row table with layernorm. 1 warp/row, NROWP rows (pad rows zeroed).
__global__ void k_buildtab(const float* __restrict__ lg, const float* __restrict__ lb) {
    int r = (blockIdx.x * blockDim.x + threadIdx.x) >> 5;
    int lane = threadIdx.x & 31;
    if (r >= NROWP) return;
    if (r >= NROW) {
        *(float4*)(g_x0t + r * 128 + lane * 4) = make_float4(0.f, 0.f, 0.f, 0.f);
        return;
    }
    const float* src = (r < 51) ? (g_embproj + r * 128) : (g_start + (r - 51) * 128);
    float4 x = *(const float4*)(src + lane * 4);
    float mu = warp_sum(x.x + x.y + x.z + x.w) * (1.f / 128.f);
    float dx = x.x - mu, dy = x.y - mu, dz = x.z - mu, dw = x.w - mu;
    float var = warp_sum(dx * dx + dy * dy + dz * dz + dw * dw) * (1.f / 128.f);
    float inv = rsqrtf(var + 1e-6f);
    float4 gv = *(const float4*)(lg + lane * 4);
    float4 bv = *(const float4*)(lb + lane * 4);
    float4 o;
    o.x = dx * inv * gv.x + bv.x;
    o.y = dy * inv * gv.y + bv.y;
    o.z = dz * inv * gv.z + bv.z;
    o.w = dw * inv * gv.w + bv.w;
    *(float4*)(g_x0t + r * 128 + lane * 4) = o;
}

// node -> row id
__global__ void k_rid(const int* __restrict__ m_idx) {
    int n = blockIdx.x * blockDim.x + threadIdx.x;
    if (n >= NN) return;
    int local = n & 63, g = n >> 6;
    g_rid[n] = (local == 0) ? (51 + g) : m_idx[n];
}

// ---------------- edge CSR (counting sort by dst) ----------------
__global__ void k_zero() {
    int i = blockIdx.x * blockDim.x + threadIdx.x;
    if (i < NN) g_cnt[i] = 0;
}
__global__ void k_hist(const int* __restrict__ dst) {
    int e = blockIdx.x * blockDim.x + threadIdx.x;
    if (e < EE) atomicAdd(&g_cnt[dst[e]], 1);
}
__global__ void k_scan() {
    __shared__ int ss[1024];
    int t = threadIdx.x;
    int base = t * 32;
    int c[32];
    int s = 0;
#pragma unroll
    for (int i = 0; i < 32; i++) { c[i] = g_cnt[base + i]; s += c[i]; }
    ss[t] = s;
    __syncthreads();
    for (int off = 1; off < 1024; off <<= 1) {
        int v = (t >= off) ? ss[t - off] : 0;
        __syncthreads();
        ss[t] += v;
        __syncthreads();
    }
    int run = ss[t] - s;
#pragma unroll
    for (int i = 0; i < 32; i++) {
        g_rowptr[base + i] = run;
        g_cursor[base + i] = run;
        run += c[i];
    }
    if (t == 1023) g_rowptr[NN] = run;
}
__global__ void k_scatter(const int* __restrict__ src, const int* __restrict__ dst) {
    int e = blockIdx.x * blockDim.x + threadIdx.x;
    if (e < EE) {
        int p = atomicAdd(&g_cursor[dst[e]], 1);
        g_sorted[p] = src[e];
    }
}

// ---------------- fp32 tiled GEMM: C[M,N] = A[M,K] @ B[K,N] (M,N mult of 64, K mult of 16) ----------------
__global__ void k_gemm(const float* __restrict__ A, const float* __restrict__ B,
                       float* __restrict__ C, int N, int K) {
    __shared__ float As[16][64];
    __shared__ float Bs[16][64];
    int bm = blockIdx.y * 64, bn = blockIdx.x * 64;
    int tid = threadIdx.x;
    int tx = tid & 15, ty = tid >> 4;
    float acc[4][4] = {};
    for (int k0 = 0; k0 < K; k0 += 16) {
        int r = tid >> 2, c4 = (tid & 3) << 2;
        float4 av = *(const float4*)&A[(bm + r) * K + k0 + c4];
        As[c4 + 0][r] = av.x; As[c4 + 1][r] = av.y;
        As[c4 + 2][r] = av.z; As[c4 + 3][r] = av.w;
        int br = tid >> 4, bc = (tid & 15) << 2;
        *(float4*)&Bs[br][bc] = *(const float4*)&B[(k0 + br) * N + bn + bc];
        __syncthreads();
#pragma unroll
        for (int kk = 0; kk < 16; kk++) {
            float4 a = *(const float4*)&As[kk][ty << 2];
            float4 b = *(const float4*)&Bs[kk][tx << 2];
            acc[0][0] += a.x * b.x; acc[0][1] += a.x * b.y; acc[0][2] += a.x * b.z; acc[0][3] += a.x * b.w;
            acc[1][0] += a.y * b.x; acc[1][1] += a.y * b.y; acc[1][2] += a.y * b.z; acc[1][3] += a.y * b.w;
            acc[2][0] += a.z * b.x; acc[2][1] += a.z * b.y; acc[2][2] += a.z * b.z; acc[2][3] += a.z * b.w;
            acc[3][0] += a.w * b.x; acc[3][1] += a.w * b.y; acc[3][2] += a.w * b.z; acc[3][3] += a.w * b.w;
        }
        __syncthreads();
    }
#pragma unroll
    for (int i = 0; i < 4; i++) {
        float4 o = make_float4(acc[i][0], acc[i][1], acc[i][2], acc[i][3]);
        *(float4*)&C[(bm + (ty << 2) + i) * N + bn + (tx << 2)] = o;
    }
}

// ---------------- attention coefficients on ROWS (table variant) or nodes ----------------
template <int HEADS>
__global__ void k_attn(const float* __restrict__ xp, const float* __restrict__ asrc,
                       const float* __restrict__ adst, float* __restrict__ als,
                       float* __restrict__ ald, int nrows) {
    int gw = (blockIdx.x * blockDim.x + threadIdx.x) >> 5;   // row*HEADS + h
    int lane = threadIdx.x & 31;
    if (gw >= nrows * HEADS) return;
    int h = gw % HEADS;
    const float* row = xp + gw * 128;
    float4 x = *(const float4*)(row + lane * 4);
    float4 a = *(const float4*)(asrc + h * 128 + lane * 4);
    float4 b = *(const float4*)(adst + h * 128 + lane * 4);
    float ps = warp_sum(x.x * a.x + x.y * a.y + x.z * a.z + x.w * a.w);
    float pd = warp_sum(x.x * b.x + x.y * b.y + x.z * b.z + x.w * b.w);
    if (lane == 0) { als[gw] = ps; ald[gw] = pd; }
}

// ---------------- segment softmax + aggregation + bias + elu. 1 warp/dst node ----------------
// USE_RID: xp/als/ald are indexed through g_rid (row table); else per-node.
template <int HEADS, bool USE_RID>
__global__ void k_agg(const float* __restrict__ xp, const float* __restrict__ als,
                      const float* __restrict__ ald, const float* __restrict__ bias,
                      float* __restrict__ out) {
    int d = (blockIdx.x * blockDim.x + threadIdx.x) >> 5;
    int lane = threadIdx.x & 31;
    if (d >= NN) return;
    int dr = USE_RID ? g_rid[d] : d;
    int r0 = g_rowptr[d], r1 = g_rowptr[d + 1];
    float aldd[HEADS], alsd[HEADS];
#pragma unroll
    for (int h = 0; h < HEADS; h++) {
        aldd[h] = ald[dr * HEADS + h];
        alsd[h] = als[dr * HEADS + h];
    }
    // pass 1: segment max (incl. self loop)
    float m[HEADS];
#pragma unroll
    for (int h = 0; h < HEADS; h++) m[h] = lrelu02(alsd[h] + aldd[h]);
    for (int e = r0 + lane; e < r1; e += 32) {
        int s = g_sorted[e];
        int sr = USE_RID ? g_rid[s] : s;
#pragma unroll
        for (int h = 0; h < HEADS; h++)
            m[h] = fmaxf(m[h], lrelu02(als[sr * HEADS + h] + aldd[h]));
    }
#pragma unroll
    for (int h = 0; h < HEADS; h++) m[h] = warp_max(m[h]);

    // pass 2: denom + weighted message sum
    float denom[HEADS];
    float acc[HEADS * 4];
#pragma unroll
    for (int i = 0; i < HEADS * 4; i++) acc[i] = 0.f;
    {   // self loop
        float w[HEADS];
#pragma unroll
        for (int h = 0; h < HEADS; h++) {
            w[h] = expf(lrelu02(alsd[h] + aldd[h]) - m[h]);
            denom[h] = w[h];
        }
        const float* rowp = xp + dr * HEADS * 128;
#pragma unroll
        for (int h = 0; h < HEADS; h++) {
            float4 xv = *(const float4*)(rowp + h * 128 + lane * 4);
            acc[h * 4 + 0] += w[h] * xv.x; acc[h * 4 + 1] += w[h] * xv.y;
            acc[h * 4 + 2] += w[h] * xv.z; acc[h * 4 + 3] += w[h] * xv.w;
        }
    }
    for (int e = r0; e < r1; e++) {
        int s = g_sorted[e];   // warp-uniform
        int sr = USE_RID ? g_rid[s] : s;
        float w[HEADS];
#pragma unroll
        for (int h = 0; h < HEADS; h++) {
            w[h] = expf(lrelu02(als[sr * HEADS + h] + aldd[h]) - m[h]);
            denom[h] += w[h];
        }
        const float* rowp = xp + sr * HEADS * 128;
#pragma unroll
        for (int h = 0; h < HEADS; h++) {
            float4 xv = *(const float4*)(rowp + h * 128 + lane * 4);
            acc[h * 4 + 0] += w[h] * xv.x; acc[h * 4 + 1] += w[h] * xv.y;
            acc[h * 4 + 2] += w[h] * xv.z; acc[h * 4 + 3] += w[h] * xv.w;
        }
    }
#pragma unroll
    for (int h = 0; h < HEADS; h++) {
        float inv = 1.f / denom[h];
        float4 bv = *(const float4*)(bias + h * 128 + lane * 4);
        float4 o;
        o.x = elu1(acc[h * 4 + 0] * inv + bv.x);
        o.y = elu1(acc[h * 4 + 1] * inv + bv.y);
        o.z = elu1(acc[h * 4 + 2] * inv + bv.z);
        o.w = elu1(acc[h * 4 + 3] * inv + bv.w);
        *(float4*)(out + d * HEADS * 128 + h * 128 + lane * 4) = o;
    }
}

// ---------------- masked mean pooling ----------------
__global__ void k_pool(const int* __restrict__ m_idx) {
    int g = blockIdx.x, j = threadIdx.x;   // 128 threads
    float s = 0.f;
    int cnt = 0;
    for (int n = 0; n < MAXNODE; n++) {
        int node = g * MAXNODE + n;
        if (m_idx[node] >= 1) { s += g_x2[node * 128 + j]; cnt++; }
    }
    g_pooled[g * 128 + j] = s / (float)cnt;
}

// ---------------- output head ----------------
__global__ void k_head(const float* __restrict__ Wo1, const float* __restrict__ bo1,
                       const float* __restrict__ Wo2, const float* __restrict__ bo2,
                       float* __restrict__ out) {
    int g = blockIdx.x, j = threadIdx.x;   // 128 threads
    __shared__ float sp[128];
    __shared__ float red[128];
    sp[j] = g_pooled[g * 128 + j];
    __syncthreads();
    float acc = 0.f;
    for (int k = 0; k < 128; k++) acc += sp[k] * Wo1[k * 128 + j];
    acc += bo1[j];
    float h1 = acc > 0.f ? acc : 0.01f * acc;
    red[j] = h1 * Wo2[j];
    __syncthreads();
    for (int off = 64; off > 0; off >>= 1) {
        if (j < off) red[j] += red[j + off];
        __syncthreads();
    }
    if (j == 0) out[g] = red[0] + bo2[0];
}

// ---------------- host ----------------
extern "C" void kernel_launch(void* const* d_in, const int* in_sizes, int n_in,
                              void* d_out, int out_size) {
    int it, iv, im, iei, iWt, ibt, iWv, ibv, iemb, iWn, ibn, iWs, ibs, ilg, ilb;
    int iW1, ias1, iad1, ib1, iW2, ias2, iad2, ib2, iWo1, ibo1, iWo2, ibo2;
    if (in_sizes[2] == NN) {   // setup_inputs dict order
        it = 0; iv = 1; im = 2; iei = 3; iWt = 4; ibt = 5; iWv = 6; ibv = 7;
        iemb = 8; iWn = 9; ibn = 10; iWs = 11; ibs = 12; ilg = 13; ilb = 14;
        iW1 = 15; ias1 = 16; iad1 = 17; ib1 = 18; iW2 = 19; ias2 = 20; iad2 = 21;
        ib2 = 22; iWo1 = 23; ibo1 = 24; iWo2 = 25; ibo2 = 26;
    } else {                   // reference() signature order
        it = 0; iv = 1; iWt = 2; ibt = 3; iWv = 4; ibv = 5; iemb = 6; iWn = 7;
        ibn = 8; iWs = 9; ibs = 10; ilg = 11; ilb = 12; iW1 = 13; ias1 = 14;
        iad1 = 15; ib1 = 16; iW2 = 17; ias2 = 18; iad2 = 19; ib2 = 20;
        iWo1 = 21; ibo1 = 22; iWo2 = 23; ibo2 = 24; im = 25; iei = 26;
    }
    const float* t   = (const float*)d_in[it];
    const float* v   = (const float*)d_in[iv];
    const int*   mi  = (const int*)d_in[im];
    const int*   ei  = (const int*)d_in[iei];
    const float* Wt  = (const float*)d_in[iWt];
    const float* bt  = (const float*)d_in[ibt];
    const float* Wv  = (const float*)d_in[iWv];
    const float* bv  = (const float*)d_in[ibv];
    const float* emb = (const float*)d_in[iemb];
    const float* Wn  = (const float*)d_in[iWn];
    const float* bn  = (const float*)d_in[ibn];
    const float* Ws  = (const float*)d_in[iWs];
    const float* bs  = (const float*)d_in[ibs];
    const float* lg  = (const float*)d_in[ilg];
    const float* lb  = (const float*)d_in[ilb];
    const float* W1  = (const float*)d_in[iW1];
    const float* as1 = (const float*)d_in[ias1];
    const float* ad1 = (const float*)d_in[iad1];
    const float* b1  = (const float*)d_in[ib1];
    const float* W2  = (const float*)d_in[iW2];
    const float* as2 = (const float*)d_in[ias2];
    const float* ad2 = (const float*)d_in[iad2];
    const float* b2  = (const float*)d_in[ib2];
    const float* Wo1 = (const float*)d_in[iWo1];
    const float* bo1 = (const float*)d_in[ibo1];
    const float* Wo2 = (const float*)d_in[iWo2];
    const float* bo2 = (const float*)d_in[ibo2];
    const int* esrc = ei;
    const int* edst = ei + EE;

    float *p_x0t, *p_xp1t, *p_x1, *p_als1, *p_ald1, *p_xp2, *p_x2, *p_als2, *p_ald2;
    cudaGetSymbolAddress((void**)&p_x0t, g_x0t);
    cudaGetSymbolAddress((void**)&p_xp1t, g_xp1t);
    cudaGetSymbolAddress((void**)&p_x1, g_x1);
    cudaGetSymbolAddress((void**)&p_als1, g_als1);
    cudaGetSymbolAddress((void**)&p_ald1, g_ald1);
    cudaGetSymbolAddress((void**)&p_xp2, g_xp2);
    cudaGetSymbolAddress((void**)&p_x2, g_x2);
    cudaGetSymbolAddress((void**)&p_als2, g_als2);
    cudaGetSymbolAddress((void**)&p_ald2, g_ald2);

    // stage 1: embeds + row table + layernorm
    k_tv<<<GG / 4, 256>>>(t, v, Wt, bt, Wv, bv);
    k_start<<<GG / 4, 128>>>(Ws, bs);
    k_embproj<<<51, 128>>>(emb, Wn, bn);
    k_buildtab<<<(NROWP * 32 + 255) / 256, 256>>>(lg, lb);
    k_rid<<<NN / 256, 256>>>(mi);

    // edge CSR (independent of features)
    k_zero<<<NN / 256, 256>>>();
    k_hist<<<EE / 256, 256>>>(edst);
    k_scan<<<1, 1024>>>();
    k_scatter<<<EE / 256, 256>>>(esrc, edst);

    // conv1 on the 563-row table: xp1t = x0t @ W1 (M=576, K=128, N=512)
    k_gemm<<<dim3(8, NROWP / 64), 256>>>(p_x0t, W1, p_xp1t, 512, 128);
    k_attn<4><<<(NROW * 4 * 32 + 255) / 256, 256>>>(p_xp1t, as1, ad1, p_als1, p_ald1, NROW);
    k_agg<4, true><<<(NN * 32) / 256, 256>>>(p_xp1t, p_als1, p_ald1, b1, p_x1);

    // conv2: xp2 = x1 @ W2 (M=NN, K=512, N=128) — per-node, not dedupable
    k_gemm<<<dim3(2, NN / 64), 256>>>(p_x1, W2, p_xp2, 128, 512);
    k_attn<1><<<(NN * 32) / 256, 256>>>(p_xp2, as2, ad2, p_als2, p_ald2, NN);
    k_agg<1, false><<<(NN * 32) / 256, 256>>>(p_xp2, p_als2, p_ald2, b2, p_x2);

    // pool + head
    k_pool<<<GG, 128>>>(mi);
    k_head<<<GG, 128>>>(Wo1, bo1, Wo2, bo2, (float*)d_out);
}

// round 8
// speedup vs baseline: 1.4305x; 1.1028x over previous
#include <cuda_runtime.h>
#include <math.h>

#define NN 32768
#define GG 512
#define MAXNODE 64
#define EE 262144
#define NROW 563            // 51 type rows + 512 start rows
#define NROWP 576           // padded to 64 multiple for GEMM tiles

// ---------------- scratch (static device globals; no allocation) ----------------
__device__ float g_tv[GG * 256];          // [ve | te] per graph
__device__ float g_start[GG * 128];
__device__ float g_embproj[51 * 128];
__device__ float g_x0t[NROWP * 128];      // layernormed distinct rows (table)
__device__ float g_xp1t[NROWP * 512];     // x0_table @ W1
__device__ float g_x1[NN * 512];          // conv1 output (post elu, per node)
__device__ float g_als1[NROWP * 4];
__device__ float g_ald1[NROWP * 4];
__device__ float g_xp2[NN * 128];         // x1 @ W2
__device__ float g_x2[NN * 128];          // conv2 output
__device__ float g_als2[NN];
__device__ float g_ald2[NN];
__device__ int   g_rid[NN];               // node -> distinct row id
__device__ int   g_cnt[NN];
__device__ int   g_rowptr[NN + 1];
__device__ int   g_cursor[NN];
__device__ int   g_sorted[EE];            // src sorted by dst
__device__ float g_pooled[GG * 128];

// ---------------- helpers ----------------
__device__ __forceinline__ float warp_sum(float v) {
#pragma unroll
    for (int o = 16; o > 0; o >>= 1) v += __shfl_xor_sync(0xffffffffu, v, o);
    return v;
}
__device__ __forceinline__ float warp_max(float v) {
#pragma unroll
    for (int o = 16; o > 0; o >>= 1) v = fmaxf(v, __shfl_xor_sync(0xffffffffu, v, o));
    return v;
}
__device__ __forceinline__ float lrelu02(float x) { return x > 0.f ? x : 0.2f * x; }
__device__ __forceinline__ float elu1(float x) { return x > 0.f ? x : (__expf(x) - 1.f); }

// ---------------- stage 1: graph-level embeds ----------------
__global__ void k_tv(const float* __restrict__ t, const float* __restrict__ v,
                     const float* __restrict__ Wt, const float* __restrict__ bt,
                     const float* __restrict__ Wv, const float* __restrict__ bv) {
    const int GT = 4;
    __shared__ float sv[GT][768];
    __shared__ float st[GT][768];
    int g0 = blockIdx.x * GT;
    for (int i = threadIdx.x; i < GT * 768; i += 256) {
        int gi = i / 768, k = i - gi * 768;
        sv[gi][k] = v[(g0 + gi) * 768 + k];
        st[gi][k] = t[(g0 + gi) * 768 + k];
    }
    __syncthreads();
    int j = threadIdx.x;
    int col = j & 127;
    bool isv = (j < 128);
    const float* W = isv ? Wv : Wt;
    float (*S)[768] = isv ? sv : st;
    float acc[GT] = {0.f, 0.f, 0.f, 0.f};
    for (int k = 0; k < 768; k++) {
        float w = W[k * 128 + col];
#pragma unroll
        for (int gi = 0; gi < GT; gi++) acc[gi] += S[gi][k] * w;
    }
    float b = isv ? bv[col] : bt[col];
#pragma unroll
    for (int gi = 0; gi < GT; gi++) g_tv[(g0 + gi) * 256 + j] = acc[gi] + b;
}

__global__ void k_start(const float* __restrict__ Ws, const float* __restrict__ bs) {
    const int GT = 4;
    __shared__ float s[GT][256];
    int g0 = blockIdx.x * GT;
    for (int i = threadIdx.x; i < GT * 256; i += 128) ((float*)s)[i] = g_tv[g0 * 256 + i];
    __syncthreads();
    int j = threadIdx.x;
    float acc[GT] = {0.f, 0.f, 0.f, 0.f};
    for (int k = 0; k < 256; k++) {
        float w = Ws[k * 128 + j];
#pragma unroll
        for (int gi = 0; gi < GT; gi++) acc[gi] += s[gi][k] * w;
    }
    float b = bs[j];
#pragma unroll
    for (int gi = 0; gi < GT; gi++) g_start[(g0 + gi) * 128 + j] = acc[gi] + b;
}

__global__ void k_embproj(const float* __restrict__ emb, const float* __restrict__ Wn,
                          const float* __restrict__ bn) {
    __shared__ float se[128];
    int j = threadIdx.x;
    se[j] = emb[blockIdx.x * 128 + j];
    __syncthreads();
    float acc = 0.f;
    for (int k = 0; k < 128; k++) acc += se[k] * Wn[k * 128 + j];
    g_embproj[blockIdx.x * 128 + j] = acc + bn[j];
}

// build distinct-row table with layernorm. 1 warp/row, NROWP rows (pad rows zeroed).
__global__ void k_buildtab(const float* __restrict__ lg, const float* __restrict__ lb) {
    int r = (blockIdx.x * blockDim.x + threadIdx.x) >> 5;
    int lane = threadIdx.x & 31;
    if (r >= NROWP) return;
    if (r >= NROW) {
        *(float4*)(g_x0t + r * 128 + lane * 4) = make_float4(0.f, 0.f, 0.f, 0.f);
        return;
    }
    const float* src = (r < 51) ? (g_embproj + r * 128) : (g_start + (r - 51) * 128);
    float4 x = *(const float4*)(src + lane * 4);
    float mu = warp_sum(x.x + x.y + x.z + x.w) * (1.f / 128.f);
    float dx = x.x - mu, dy = x.y - mu, dz = x.z - mu, dw = x.w - mu;
    float var = warp_sum(dx * dx + dy * dy + dz * dz + dw * dw) * (1.f / 128.f);
    float inv = rsqrtf(var + 1e-6f);
    float4 gv = *(const float4*)(lg + lane * 4);
    float4 bv = *(const float4*)(lb + lane * 4);
    float4 o;
    o.x = dx * inv * gv.x + bv.x;
    o.y = dy * inv * gv.y + bv.y;
    o.z = dz * inv * gv.z + bv.z;
    o.w = dw * inv * gv.w + bv.w;
    *(float4*)(g_x0t + r * 128 + lane * 4) = o;
}

// node -> row id
__global__ void k_rid(const int* __restrict__ m_idx) {
    int n = blockIdx.x * blockDim.x + threadIdx.x;
    if (n >= NN) return;
    int local = n & 63, g = n >> 6;
    g_rid[n] = (local == 0) ? (51 + g) : m_idx[n];
}

// ---------------- edge CSR (counting sort by dst) ----------------
__global__ void k_zero() {
    int i = blockIdx.x * blockDim.x + threadIdx.x;
    if (i < NN) g_cnt[i] = 0;
}
__global__ void k_hist(const int* __restrict__ dst) {
    int e = blockIdx.x * blockDim.x + threadIdx.x;
    if (e < EE) atomicAdd(&g_cnt[dst[e]], 1);
}
__global__ void k_scan() {
    __shared__ int ss[1024];
    int t = threadIdx.x;
    int base = t * 32;
    int c[32];
    int s = 0;
#pragma unroll
    for (int i = 0; i < 32; i++) { c[i] = g_cnt[base + i]; s += c[i]; }
    ss[t] = s;
    __syncthreads();
    for (int off = 1; off < 1024; off <<= 1) {
        int v = (t >= off) ? ss[t - off] : 0;
        __syncthreads();
        ss[t] += v;
        __syncthreads();
    }
    int run = ss[t] - s;
#pragma unroll
    for (int i = 0; i < 32; i++) {
        g_rowptr[base + i] = run;
        g_cursor[base + i] = run;
        run += c[i];
    }
    if (t == 1023) g_rowptr[NN] = run;
}
__global__ void k_scatter(const int* __restrict__ src, const int* __restrict__ dst) {
    int e = blockIdx.x * blockDim.x + threadIdx.x;
    if (e < EE) {
        int p = atomicAdd(&g_cursor[dst[e]], 1);
        g_sorted[p] = src[e];
    }
}

// ---------------- small fp32 tiled GEMM (64x64) for conv1 table ----------------
__global__ void k_gemm(const float* __restrict__ A, const float* __restrict__ B,
                       float* __restrict__ C, int N, int K) {
    __shared__ float As[16][64];
    __shared__ float Bs[16][64];
    int bm = blockIdx.y * 64, bn = blockIdx.x * 64;
    int tid = threadIdx.x;
    int tx = tid & 15, ty = tid >> 4;
    float acc[4][4] = {};
    for (int k0 = 0; k0 < K; k0 += 16) {
        int r = tid >> 2, c4 = (tid & 3) << 2;
        float4 av = *(const float4*)&A[(bm + r) * K + k0 + c4];
        As[c4 + 0][r] = av.x; As[c4 + 1][r] = av.y;
        As[c4 + 2][r] = av.z; As[c4 + 3][r] = av.w;
        int br = tid >> 4, bc = (tid & 15) << 2;
        *(float4*)&Bs[br][bc] = *(const float4*)&B[(k0 + br) * N + bn + bc];
        __syncthreads();
#pragma unroll
        for (int kk = 0; kk < 16; kk++) {
            float4 a = *(const float4*)&As[kk][ty << 2];
            float4 b = *(const float4*)&Bs[kk][tx << 2];
            acc[0][0] += a.x * b.x; acc[0][1] += a.x * b.y; acc[0][2] += a.x * b.z; acc[0][3] += a.x * b.w;
            acc[1][0] += a.y * b.x; acc[1][1] += a.y * b.y; acc[1][2] += a.y * b.z; acc[1][3] += a.y * b.w;
            acc[2][0] += a.z * b.x; acc[2][1] += a.z * b.y; acc[2][2] += a.z * b.z; acc[2][3] += a.z * b.w;
            acc[3][0] += a.w * b.x; acc[3][1] += a.w * b.y; acc[3][2] += a.w * b.z; acc[3][3] += a.w * b.w;
        }
        __syncthreads();
    }
#pragma unroll
    for (int i = 0; i < 4; i++) {
        float4 o = make_float4(acc[i][0], acc[i][1], acc[i][2], acc[i][3]);
        *(float4*)&C[(bm + (ty << 2) + i) * N + bn + (tx << 2)] = o;
    }
}

// ---------------- big fp32 GEMM: 128x128 tile, 8x8 micro (split cols), dbl-buffered ----------------
// C[M,128] = A[M,K] @ B[K,128]; M mult of 128, K mult of 16, N fixed 128.
// A-tile padded to 132 floats/row (528B = 33*16 -> float4-aligned rows).
// Thread (tx,ty) owns rows ty*8..+7, cols {tx*4..+3, 64+tx*4..+3}.
__global__ __launch_bounds__(256, 2) void k_gemm128(
    const float* __restrict__ A, const float* __restrict__ B,
    float* __restrict__ C, int K) {
    __shared__ float As[2][16][132];
    __shared__ float Bs[2][16][128];
    const int N = 128;
    int bm = blockIdx.x * 128;
    int tid = threadIdx.x;
    int tx = tid & 15, ty = tid >> 4;          // micro tile coords
    int ar = tid >> 1, ac = (tid & 1) * 8;     // A load: row 0..127, col base 0/8
    int br = tid >> 4, bc = (tid & 15) * 8;    // B load: row 0..15, col base

    float acc[8][8] = {};
    float4 pa0, pa1, pb0, pb1;

    // preload tile 0
    pa0 = *(const float4*)&A[(bm + ar) * K + ac];
    pa1 = *(const float4*)&A[(bm + ar) * K + ac + 4];
    pb0 = *(const float4*)&B[br * N + bc];
    pb1 = *(const float4*)&B[br * N + bc + 4];
    As[0][ac + 0][ar] = pa0.x; As[0][ac + 1][ar] = pa0.y;
    As[0][ac + 2][ar] = pa0.z; As[0][ac + 3][ar] = pa0.w;
    As[0][ac + 4][ar] = pa1.x; As[0][ac + 5][ar] = pa1.y;
    As[0][ac + 6][ar] = pa1.z; As[0][ac + 7][ar] = pa1.w;
    *(float4*)&Bs[0][br][bc] = pb0;
    *(float4*)&Bs[0][br][bc + 4] = pb1;
    __syncthreads();

    int KT = K >> 4;
    for (int kt = 0; kt < KT; kt++) {
        int cur = kt & 1;
        if (kt + 1 < KT) {
            int k0 = (kt + 1) << 4;
            pa0 = *(const float4*)&A[(bm + ar) * K + k0 + ac];
            pa1 = *(const float4*)&A[(bm + ar) * K + k0 + ac + 4];
            pb0 = *(const float4*)&B[(k0 + br) * N + bc];
            pb1 = *(const float4*)&B[(k0 + br) * N + bc + 4];
        }
#pragma unroll
        for (int kk = 0; kk < 16; kk++) {
            float4 a0 = *(const float4*)&As[cur][kk][ty * 8];
            float4 a1 = *(const float4*)&As[cur][kk][ty * 8 + 4];
            float4 b0 = *(const float4*)&Bs[cur][kk][tx * 4];        // cols tx*4..+3
            float4 b1 = *(const float4*)&Bs[cur][kk][tx * 4 + 64];   // cols 64+tx*4..+3
            float av[8] = {a0.x, a0.y, a0.z, a0.w, a1.x, a1.y, a1.z, a1.w};
            float bv[8] = {b0.x, b0.y, b0.z, b0.w, b1.x, b1.y, b1.z, b1.w};
#pragma unroll
            for (int i = 0; i < 8; i++)
#pragma unroll
                for (int j = 0; j < 8; j++) acc[i][j] += av[i] * bv[j];
        }
        if (kt + 1 < KT) {
            int nxt = cur ^ 1;
            As[nxt][ac + 0][ar] = pa0.x; As[nxt][ac + 1][ar] = pa0.y;
            As[nxt][ac + 2][ar] = pa0.z; As[nxt][ac + 3][ar] = pa0.w;
            As[nxt][ac + 4][ar] = pa1.x; As[nxt][ac + 5][ar] = pa1.y;
            As[nxt][ac + 6][ar] = pa1.z; As[nxt][ac + 7][ar] = pa1.w;
            *(float4*)&Bs[nxt][br][bc] = pb0;
            *(float4*)&Bs[nxt][br][bc + 4] = pb1;
        }
        __syncthreads();
    }
#pragma unroll
    for (int i = 0; i < 8; i++) {
        float4 o0 = make_float4(acc[i][0], acc[i][1], acc[i][2], acc[i][3]);
        float4 o1 = make_float4(acc[i][4], acc[i][5], acc[i][6], acc[i][7]);
        float* crow = &C[(bm + ty * 8 + i) * N];
        *(float4*)(crow + tx * 4) = o0;
        *(float4*)(crow + tx * 4 + 64) = o1;
    }
}

// ---------------- attention coefficients ----------------
template <int HEADS>
__global__ void k_attn(const float* __restrict__ xp, const float* __restrict__ asrc,
                       const float* __restrict__ adst, float* __restrict__ als,
                       float* __restrict__ ald, int nrows) {
    int gw = (blockIdx.x * blockDim.x + threadIdx.x) >> 5;   // row*HEADS + h
    int lane = threadIdx.x & 31;
    if (gw >= nrows * HEADS) return;
    int h = gw % HEADS;
    const float* row = xp + gw * 128;
    float4 x = *(const float4*)(row + lane * 4);
    float4 a = *(const float4*)(asrc + h * 128 + lane * 4);
    float4 b = *(const float4*)(adst + h * 128 + lane * 4);
    float ps = warp_sum(x.x * a.x + x.y * a.y + x.z * a.z + x.w * a.w);
    float pd = warp_sum(x.x * b.x + x.y * b.y + x.z * b.z + x.w * b.w);
    if (lane == 0) { als[gw] = ps; ald[gw] = pd; }
}

// ---------------- segment softmax + aggregation. ONE WARP PER (node, head) ----------------
// USE_RID: xp/als/ald indexed through g_rid (row table); else per-node.
template <int HEADS, bool USE_RID>
__global__ void k_agg(const float* __restrict__ xp, const float* __restrict__ als,
                      const float* __restrict__ ald, const float* __restrict__ bias,
                      float* __restrict__ out) {
    int gw = (blockIdx.x * blockDim.x + threadIdx.x) >> 5;  // node*HEADS + h
    int lane = threadIdx.x & 31;
    if (gw >= NN * HEADS) return;
    int d = gw / HEADS, h = gw % HEADS;
    int dr = USE_RID ? g_rid[d] : d;
    int r0 = g_rowptr[d], r1 = g_rowptr[d + 1];
    float aldd = ald[dr * HEADS + h];
    float alsd = als[dr * HEADS + h];
    float self_s = lrelu02(alsd + aldd);

    // pass 1: segment max (incl. self loop)
    float m = self_s;
    for (int e = r0 + lane; e < r1; e += 32) {
        int s = g_sorted[e];
        int sr = USE_RID ? g_rid[s] : s;
        m = fmaxf(m, lrelu02(als[sr * HEADS + h] + aldd));
    }
    m = warp_max(m);

    // pass 2: denom + weighted message sum
    float w = __expf(self_s - m);
    float denom = w;
    const float* rowp = xp + (dr * HEADS + h) * 128;
    float4 xv = *(const float4*)(rowp + lane * 4);
    float4 acc;
    acc.x = w * xv.x; acc.y = w * xv.y; acc.z = w * xv.z; acc.w = w * xv.w;
    for (int e = r0; e < r1; e++) {
        int s = g_sorted[e];   // warp-uniform
        int sr = USE_RID ? g_rid[s] : s;
        w = __expf(lrelu02(als[sr * HEADS + h] + aldd) - m);
        denom += w;
        const float* rp = xp + (sr * HEADS + h) * 128;
        float4 v = *(const float4*)(rp + lane * 4);
        acc.x += w * v.x; acc.y += w * v.y; acc.z += w * v.z; acc.w += w * v.w;
    }
    float inv = 1.f / denom;
    float4 bv = *(const float4*)(bias + h * 128 + lane * 4);
    float4 o;
    o.x = elu1(acc.x * inv + bv.x);
    o.y = elu1(acc.y * inv + bv.y);
    o.z = elu1(acc.z * inv + bv.z);
    o.w = elu1(acc.w * inv + bv.w);
    *(float4*)(out + (d * HEADS + h) * 128 + lane * 4) = o;
}

// ---------------- masked mean pooling ----------------
__global__ void k_pool(const int* __restrict__ m_idx) {
    int g = blockIdx.x, j = threadIdx.x;   // 128 threads
    float s = 0.f;
    int cnt = 0;
    for (int n = 0; n < MAXNODE; n++) {
        int node = g * MAXNODE + n;
        if (m_idx[node] >= 1) { s += g_x2[node * 128 + j]; cnt++; }
    }
    g_pooled[g * 128 + j] = s / (float)cnt;
}

// ---------------- output head ----------------
__global__ void k_head(const float* __restrict__ Wo1, const float* __restrict__ bo1,
                       const float* __restrict__ Wo2, const float* __restrict__ bo2,
                       float* __restrict__ out) {
    int g = blockIdx.x, j = threadIdx.x;   // 128 threads
    __shared__ float sp[128];
    __shared__ float red[128];
    sp[j] = g_pooled[g * 128 + j];
    __syncthreads();
    float acc = 0.f;
    for (int k = 0; k < 128; k++) acc += sp[k] * Wo1[k * 128 + j];
    acc += bo1[j];
    float h1 = acc > 0.f ? acc : 0.01f * acc;
    red[j] = h1 * Wo2[j];
    __syncthreads();
    for (int off = 64; off > 0; off >>= 1) {
        if (j < off) red[j] += red[j + off];
        __syncthreads();
    }
    if (j == 0) out[g] = red[0] + bo2[0];
}

// ---------------- host ----------------
extern "C" void kernel_launch(void* const* d_in, const int* in_sizes, int n_in,
                              void* d_out, int out_size) {
    int it, iv, im, iei, iWt, ibt, iWv, ibv, iemb, iWn, ibn, iWs, ibs, ilg, ilb;
    int iW1, ias1, iad1, ib1, iW2, ias2, iad2, ib2, iWo1, ibo1, iWo2, ibo2;
    if (in_sizes[2] == NN) {   // setup_inputs dict order
        it = 0; iv = 1; im = 2; iei = 3; iWt = 4; ibt = 5; iWv = 6; ibv = 7;
        iemb = 8; iWn = 9; ibn = 10; iWs = 11; ibs = 12; ilg = 13; ilb = 14;
        iW1 = 15; ias1 = 16; iad1 = 17; ib1 = 18; iW2 = 19; ias2 = 20; iad2 = 21;
        ib2 = 22; iWo1 = 23; ibo1 = 24; iWo2 = 25; ibo2 = 26;
    } else {                   // reference() signature order
        it = 0; iv = 1; iWt = 2; ibt = 3; iWv = 4; ibv = 5; iemb = 6; iWn = 7;
        ibn = 8; iWs = 9; ibs = 10; ilg = 11; ilb = 12; iW1 = 13; ias1 = 14;
        iad1 = 15; ib1 = 16; iW2 = 17; ias2 = 18; iad2 = 19; ib2 = 20;
        iWo1 = 21; ibo1 = 22; iWo2 = 23; ibo2 = 24; im = 25; iei = 26;
    }
    const float* t   = (const float*)d_in[it];
    const float* v   = (const float*)d_in[iv];
    const int*   mi  = (const int*)d_in[im];
    const int*   ei  = (const int*)d_in[iei];
    const float* Wt  = (const float*)d_in[iWt];
    const float* bt  = (const float*)d_in[ibt];
    const float* Wv  = (const float*)d_in[iWv];
    const float* bv  = (const float*)d_in[ibv];
    const float* emb = (const float*)d_in[iemb];
    const float* Wn  = (const float*)d_in[iWn];
    const float* bn  = (const float*)d_in[ibn];
    const float* Ws  = (const float*)d_in[iWs];
    const float* bs  = (const float*)d_in[ibs];
    const float* lg  = (const float*)d_in[ilg];
    const float* lb  = (const float*)d_in[ilb];
    const float* W1  = (const float*)d_in[iW1];
    const float* as1 = (const float*)d_in[ias1];
    const float* ad1 = (const float*)d_in[iad1];
    const float* b1  = (const float*)d_in[ib1];
    const float* W2  = (const float*)d_in[iW2];
    const float* as2 = (const float*)d_in[ias2];
    const float* ad2 = (const float*)d_in[iad2];
    const float* b2  = (const float*)d_in[ib2];
    const float* Wo1 = (const float*)d_in[iWo1];
    const float* bo1 = (const float*)d_in[ibo1];
    const float* Wo2 = (const float*)d_in[iWo2];
    const float* bo2 = (const float*)d_in[ibo2];
    const int* esrc = ei;
    const int* edst = ei + EE;

    float *p_x0t, *p_xp1t, *p_x1, *p_als1, *p_ald1, *p_xp2, *p_x2, *p_als2, *p_ald2;
    cudaGetSymbolAddress((void**)&p_x0t, g_x0t);
    cudaGetSymbolAddress((void**)&p_xp1t, g_xp1t);
    cudaGetSymbolAddress((void**)&p_x1, g_x1);
    cudaGetSymbolAddress((void**)&p_als1, g_als1);
    cudaGetSymbolAddress((void**)&p_ald1, g_ald1);
    cudaGetSymbolAddress((void**)&p_xp2, g_xp2);
    cudaGetSymbolAddress((void**)&p_x2, g_x2);
    cudaGetSymbolAddress((void**)&p_als2, g_als2);
    cudaGetSymbolAddress((void**)&p_ald2, g_ald2);

    // stage 1: embeds + row table + layernorm
    k_tv<<<GG / 4, 256>>>(t, v, Wt, bt, Wv, bv);
    k_start<<<GG / 4, 128>>>(Ws, bs);
    k_embproj<<<51, 128>>>(emb, Wn, bn);
    k_buildtab<<<(NROWP * 32 + 255) / 256, 256>>>(lg, lb);
    k_rid<<<NN / 256, 256>>>(mi);

    // edge CSR (independent of features)
    k_zero<<<NN / 256, 256>>>();
    k_hist<<<EE / 256, 256>>>(edst);
    k_scan<<<1, 1024>>>();
    k_scatter<<<EE / 256, 256>>>(esrc, edst);

    // conv1 on the 563-row table: xp1t = x0t @ W1 (M=576, K=128, N=512)
    k_gemm<<<dim3(8, NROWP / 64), 256>>>(p_x0t, W1, p_xp1t, 512, 128);
    k_attn<4><<<(NROW * 4 * 32 + 255) / 256, 256>>>(p_xp1t, as1, ad1, p_als1, p_ald1, NROW);
    k_agg<4, true><<<(NN * 4 * 32) / 256, 256>>>(p_xp1t, p_als1, p_ald1, b1, p_x1);

    // conv2: xp2 = x1 @ W2 (M=NN, K=512, N=128) — per-node, not dedupable
    k_gemm128<<<NN / 128, 256>>>(p_x1, W2, p_xp2, 512);
    k_attn<1><<<(NN * 32) / 256, 256>>>(p_xp2, as2, ad2, p_als2, p_ald2, NN);
    k_agg<1, false><<<(NN * 32) / 256, 256>>>(p_xp2, p_als2, p_ald2, b2, p_x2);

    // pool + head
    k_pool<<<GG, 128>>>(mi);
    k_head<<<GG, 128>>>(Wo1, bo1, Wo2, bo2, (float*)d_out);
}

// round 9
// speedup vs baseline: 1.5175x; 1.0608x over previous
#include <cuda_runtime.h>
#include <cuda_bf16.h>
#include <mma.h>
#include <math.h>

using namespace nvcuda;

#define NN 32768
#define GG 512
#define MAXNODE 64
#define EE 262144
#define NROW 563            // 51 type rows + 512 start rows
#define NROWP 576           // padded to 64 multiple for GEMM tiles

// ---------------- scratch (static device globals; no allocation) ----------------
__device__ float g_tv[GG * 256];          // [ve | te] per graph
__device__ float g_start[GG * 128];
__device__ float g_embproj[51 * 128];
__device__ float g_x0t[NROWP * 128];      // layernormed distinct rows (table)
__device__ float g_xp1t[NROWP * 512];     // x0_table @ W1
__device__ __align__(16) __nv_bfloat16 g_x1h[NN * 512];   // conv1 out, bf16 hi
__device__ __align__(16) __nv_bfloat16 g_x1l[NN * 512];   // conv1 out, bf16 lo
__device__ __align__(16) __nv_bfloat16 g_w2h[512 * 128];  // W2 bf16 hi
__device__ __align__(16) __nv_bfloat16 g_w2l[512 * 128];  // W2 bf16 lo
__device__ float g_als1[NROWP * 4];
__device__ float g_ald1[NROWP * 4];
__device__ float g_xp2[NN * 128];         // x1 @ W2
__device__ float g_x2[NN * 128];          // conv2 output
__device__ float g_als2[NN];
__device__ float g_ald2[NN];
__device__ int   g_rid[NN];               // node -> distinct row id
__device__ int   g_cnt[NN];
__device__ int   g_rowptr[NN + 1];
__device__ int   g_cursor[NN];
__device__ int   g_sorted[EE];            // src sorted by dst
__device__ float g_pooled[GG * 128];

// ---------------- helpers ----------------
__device__ __forceinline__ float warp_sum(float v) {
#pragma unroll
    for (int o = 16; o > 0; o >>= 1) v += __shfl_xor_sync(0xffffffffu, v, o);
    return v;
}
__device__ __forceinline__ float warp_max(float v) {
#pragma unroll
    for (int o = 16; o > 0; o >>= 1) v = fmaxf(v, __shfl_xor_sync(0xffffffffu, v, o));
    return v;
}
__device__ __forceinline__ float lrelu02(float x) { return x > 0.f ? x : 0.2f * x; }
__device__ __forceinline__ float elu1(float x) { return x > 0.f ? x : (__expf(x) - 1.f); }

// ---------------- stage 1: graph-level embeds ----------------
__global__ void k_tv(const float* __restrict__ t, const float* __restrict__ v,
                     const float* __restrict__ Wt, const float* __restrict__ bt,
                     const float* __restrict__ Wv, const float* __restrict__ bv) {
    const int GT = 4;
    __shared__ float sv[GT][768];
    __shared__ float st[GT][768];
    int g0 = blockIdx.x * GT;
    for (int i = threadIdx.x; i < GT * 768; i += 256) {
        int gi = i / 768, k = i - gi * 768;
        sv[gi][k] = v[(g0 + gi) * 768 + k];
        st[gi][k] = t[(g0 + gi) * 768 + k];
    }
    __syncthreads();
    int j = threadIdx.x;
    int col = j & 127;
    bool isv = (j < 128);
    const float* W = isv ? Wv : Wt;
    float (*S)[768] = isv ? sv : st;
    float acc[GT] = {0.f, 0.f, 0.f, 0.f};
    for (int k = 0; k < 768; k++) {
        float w = W[k * 128 + col];
#pragma unroll
        for (int gi = 0; gi < GT; gi++) acc[gi] += S[gi][k] * w;
    }
    float b = isv ? bv[col] : bt[col];
#pragma unroll
    for (int gi = 0; gi < GT; gi++) g_tv[(g0 + gi) * 256 + j] = acc[gi] + b;
}

__global__ void k_start(const float* __restrict__ Ws, const float* __restrict__ bs) {
    const int GT = 4;
    __shared__ float s[GT][256];
    int g0 = blockIdx.x * GT;
    for (int i = threadIdx.x; i < GT * 256; i += 128) ((float*)s)[i] = g_tv[g0 * 256 + i];
    __syncthreads();
    int j = threadIdx.x;
    float acc[GT] = {0.f, 0.f, 0.f, 0.f};
    for (int k = 0; k < 256; k++) {
        float w = Ws[k * 128 + j];
#pragma unroll
        for (int gi = 0; gi < GT; gi++) acc[gi] += s[gi][k] * w;
    }
    float b = bs[j];
#pragma unroll
    for (int gi = 0; gi < GT; gi++) g_start[(g0 + gi) * 128 + j] = acc[gi] + b;
}

__global__ void k_embproj(const float* __restrict__ emb, const float* __restrict__ Wn,
                          const float* __restrict__ bn) {
    __shared__ float se[128];
    int j = threadIdx.x;
    se[j] = emb[blockIdx.x * 128 + j];
    __syncthreads();
    float acc = 0.f;
    for (int k = 0; k < 128; k++) acc += se[k] * Wn[k * 128 + j];
    g_embproj[blockIdx.x * 128 + j] = acc + bn[j];
}

// build distinct-row table with layernorm. 1 warp/row, NROWP rows (pad rows zeroed).
__global__ void k_buildtab(const float* __restrict__ lg, const float* __restrict__ lb) {
    int r = (blockIdx.x * blockDim.x + threadIdx.x) >> 5;
    int lane = threadIdx.x & 31;
    if (r >= NROWP) return;
    if (r >= NROW) {
        *(float4*)(g_x0t + r * 128 + lane * 4) = make_float4(0.f, 0.f, 0.f, 0.f);
        return;
    }
    const float* src = (r < 51) ? (g_embproj + r * 128) : (g_start + (r - 51) * 128);
    float4 x = *(const float4*)(src + lane * 4);
    float mu = warp_sum(x.x + x.y + x.z + x.w) * (1.f / 128.f);
    float dx = x.x - mu, dy = x.y - mu, dz = x.z - mu, dw = x.w - mu;
    float var = warp_sum(dx * dx + dy * dy + dz * dz + dw * dw) * (1.f / 128.f);
    float inv = rsqrtf(var + 1e-6f);
    float4 gv = *(const float4*)(lg + lane * 4);
    float4 bv = *(const float4*)(lb + lane * 4);
    float4 o;
    o.x = dx * inv * gv.x + bv.x;
    o.y = dy * inv * gv.y + bv.y;
    o.z = dz * inv * gv.z + bv.z;
    o.w = dw * inv * gv.w + bv.w;
    *(float4*)(g_x0t + r * 128 + lane * 4) = o;
}

// node -> row id
__global__ void k_rid(const int* __restrict__ m_idx) {
    int n = blockIdx.x * blockDim.x + threadIdx.x;
    if (n >= NN) return;
    int local = n & 63, g = n >> 6;
    g_rid[n] = (local == 0) ? (51 + g) : m_idx[n];
}

// ---------------- edge CSR (counting sort by dst) ----------------
__global__ void k_zero() {
    int i = blockIdx.x * blockDim.x + threadIdx.x;
    if (i < NN) g_cnt[i] = 0;
}
__global__ void k_hist(const int* __restrict__ dst) {
    int e = blockIdx.x * blockDim.x + threadIdx.x;
    if (e < EE) atomicAdd(&g_cnt[dst[e]], 1);
}
__global__ void k_scan() {
    __shared__ int ss[1024];
    int t = threadIdx.x;
    int base = t * 32;
    int c[32];
    int s = 0;
#pragma unroll
    for (int i = 0; i < 32; i++) { c[i] = g_cnt[base + i]; s += c[i]; }
    ss[t] = s;
    __syncthreads();
    for (int off = 1; off < 1024; off <<= 1) {
        int v = (t >= off) ? ss[t - off] : 0;
        __syncthreads();
        ss[t] += v;
        __syncthreads();
    }
    int run = ss[t] - s;
#pragma unroll
    for (int i = 0; i < 32; i++) {
        g_rowptr[base + i] = run;
        g_cursor[base + i] = run;
        run += c[i];
    }
    if (t == 1023) g_rowptr[NN] = run;
}
__global__ void k_scatter(const int* __restrict__ src, const int* __restrict__ dst) {
    int e = blockIdx.x * blockDim.x + threadIdx.x;
    if (e < EE) {
        int p = atomicAdd(&g_cursor[dst[e]], 1);
        g_sorted[p] = src[e];
    }
}

// ---------------- small fp32 tiled GEMM (64x64) for conv1 table ----------------
__global__ void k_gemm(const float* __restrict__ A, const float* __restrict__ B,
                       float* __restrict__ C, int N, int K) {
    __shared__ float As[16][64];
    __shared__ float Bs[16][64];
    int bm = blockIdx.y * 64, bn = blockIdx.x * 64;
    int tid = threadIdx.x;
    int tx = tid & 15, ty = tid >> 4;
    float acc[4][4] = {};
    for (int k0 = 0; k0 < K; k0 += 16) {
        int r = tid >> 2, c4 = (tid & 3) << 2;
        float4 av = *(const float4*)&A[(bm + r) * K + k0 + c4];
        As[c4 + 0][r] = av.x; As[c4 + 1][r] = av.y;
        As[c4 + 2][r] = av.z; As[c4 + 3][r] = av.w;
        int br = tid >> 4, bc = (tid & 15) << 2;
        *(float4*)&Bs[br][bc] = *(const float4*)&B[(k0 + br) * N + bn + bc];
        __syncthreads();
#pragma unroll
        for (int kk = 0; kk < 16; kk++) {
            float4 a = *(const float4*)&As[kk][ty << 2];
            float4 b = *(const float4*)&Bs[kk][tx << 2];
            acc[0][0] += a.x * b.x; acc[0][1] += a.x * b.y; acc[0][2] += a.x * b.z; acc[0][3] += a.x * b.w;
            acc[1][0] += a.y * b.x; acc[1][1] += a.y * b.y; acc[1][2] += a.y * b.z; acc[1][3] += a.y * b.w;
            acc[2][0] += a.z * b.x; acc[2][1] += a.z * b.y; acc[2][2] += a.z * b.z; acc[2][3] += a.z * b.w;
            acc[3][0] += a.w * b.x; acc[3][1] += a.w * b.y; acc[3][2] += a.w * b.z; acc[3][3] += a.w * b.w;
        }
        __syncthreads();
    }
#pragma unroll
    for (int i = 0; i < 4; i++) {
        float4 o = make_float4(acc[i][0], acc[i][1], acc[i][2], acc[i][3]);
        *(float4*)&C[(bm + (ty << 2) + i) * N + bn + (tx << 2)] = o;
    }
}

// ---------------- W2 split into bf16 hi/lo ----------------
__global__ void k_w2split(const float* __restrict__ W2) {
    int i = blockIdx.x * blockDim.x + threadIdx.x;   // 512*128 = 65536
    float v = W2[i];
    __nv_bfloat16 hi = __float2bfloat16(v);
    float lo_f = v - __bfloat162float(hi);
    g_w2h[i] = hi;
    g_w2l[i] = __float2bfloat16(lo_f);
}

// ---------------- attention coefficients ----------------
template <int HEADS>
__global__ void k_attn(const float* __restrict__ xp, const float* __restrict__ asrc,
                       const float* __restrict__ adst, float* __restrict__ als,
                       float* __restrict__ ald, int nrows) {
    int gw = (blockIdx.x * blockDim.x + threadIdx.x) >> 5;   // row*HEADS + h
    int lane = threadIdx.x & 31;
    if (gw >= nrows * HEADS) return;
    int h = gw % HEADS;
    const float* row = xp + gw * 128;
    float4 x = *(const float4*)(row + lane * 4);
    float4 a = *(const float4*)(asrc + h * 128 + lane * 4);
    float4 b = *(const float4*)(adst + h * 128 + lane * 4);
    float ps = warp_sum(x.x * a.x + x.y * a.y + x.z * a.z + x.w * a.w);
    float pd = warp_sum(x.x * b.x + x.y * b.y + x.z * b.z + x.w * b.w);
    if (lane == 0) { als[gw] = ps; ald[gw] = pd; }
}

// ---------------- conv1 agg: warp per (node,head), writes bf16 hi/lo x1 ----------------
__global__ void k_agg4bf(const float* __restrict__ xp, const float* __restrict__ als,
                         const float* __restrict__ ald, const float* __restrict__ bias) {
    const int HEADS = 4;
    int gw = (blockIdx.x * blockDim.x + threadIdx.x) >> 5;  // node*4 + h
    int lane = threadIdx.x & 31;
    if (gw >= NN * HEADS) return;
    int d = gw >> 2, h = gw & 3;
    int dr = g_rid[d];
    int r0 = g_rowptr[d], r1 = g_rowptr[d + 1];
    float aldd = ald[dr * HEADS + h];
    float alsd = als[dr * HEADS + h];
    float self_s = lrelu02(alsd + aldd);

    float m = self_s;
    for (int e = r0 + lane; e < r1; e += 32) {
        int sr = g_rid[g_sorted[e]];
        m = fmaxf(m, lrelu02(als[sr * HEADS + h] + aldd));
    }
    m = warp_max(m);

    float w = __expf(self_s - m);
    float denom = w;
    const float* rowp = xp + (dr * HEADS + h) * 128;
    float4 xv = *(const float4*)(rowp + lane * 4);
    float4 acc;
    acc.x = w * xv.x; acc.y = w * xv.y; acc.z = w * xv.z; acc.w = w * xv.w;
    for (int e = r0; e < r1; e++) {
        int sr = g_rid[g_sorted[e]];   // warp-uniform
        w = __expf(lrelu02(als[sr * HEADS + h] + aldd) - m);
        denom += w;
        const float* rp = xp + (sr * HEADS + h) * 128;
        float4 v = *(const float4*)(rp + lane * 4);
        acc.x += w * v.x; acc.y += w * v.y; acc.z += w * v.z; acc.w += w * v.w;
    }
    float inv = 1.f / denom;
    float4 bv = *(const float4*)(bias + h * 128 + lane * 4);
    float o[4];
    o[0] = elu1(acc.x * inv + bv.x);
    o[1] = elu1(acc.y * inv + bv.y);
    o[2] = elu1(acc.z * inv + bv.z);
    o[3] = elu1(acc.w * inv + bv.w);
    int idx = (d * HEADS + h) * 128 + lane * 4;
    __nv_bfloat16 hi[4], lo[4];
#pragma unroll
    for (int i = 0; i < 4; i++) {
        hi[i] = __float2bfloat16(o[i]);
        lo[i] = __float2bfloat16(o[i] - __bfloat162float(hi[i]));
    }
    *(__nv_bfloat162*)&g_x1h[idx]     = __nv_bfloat162(hi[0], hi[1]);
    *(__nv_bfloat162*)&g_x1h[idx + 2] = __nv_bfloat162(hi[2], hi[3]);
    *(__nv_bfloat162*)&g_x1l[idx]     = __nv_bfloat162(lo[0], lo[1]);
    *(__nv_bfloat162*)&g_x1l[idx + 2] = __nv_bfloat162(lo[2], lo[3]);
}

// ---------------- conv2 GEMM on tensor cores: split-bf16, fp32-equivalent ----------------
// C[NN,128] = (Ah+Al)[NN,512] @ (Bh+Bl)[512,128], dropping Al*Bl.
// Block: 64 rows x 128 cols; 8 warps in 2x4 grid, each 32x32 output (2x2 wmma 16x16).
__global__ __launch_bounds__(256) void k_wmma(float* __restrict__ C) {
    const int K = 512, N = 128;
    __shared__ __nv_bfloat16 sAh[64][40], sAl[64][40];
    __shared__ __nv_bfloat16 sBh[32][136], sBl[32][136];
    int bm = blockIdx.x * 64;
    int tid = threadIdx.x;
    int wid = tid >> 5;
    int wm = (wid & 1) * 32;
    int wn = (wid >> 1) * 32;

    wmma::fragment<wmma::accumulator, 16, 16, 16, float> acc[2][2];
#pragma unroll
    for (int i = 0; i < 2; i++)
#pragma unroll
        for (int j = 0; j < 2; j++) wmma::fill_fragment(acc[i][j], 0.f);

    int r = tid >> 2, c = (tid & 3) * 8;        // A: 64 rows x 32 cols, 8 bf16/thread
    int br = tid >> 4, bc = (tid & 15) * 8;     // B: rows br, br+16

    for (int k0 = 0; k0 < K; k0 += 32) {
        *(uint4*)&sAh[r][c] = *(const uint4*)&g_x1h[(bm + r) * K + k0 + c];
        *(uint4*)&sAl[r][c] = *(const uint4*)&g_x1l[(bm + r) * K + k0 + c];
        *(uint4*)&sBh[br][bc]      = *(const uint4*)&g_w2h[(k0 + br) * N + bc];
        *(uint4*)&sBh[br + 16][bc] = *(const uint4*)&g_w2h[(k0 + br + 16) * N + bc];
        *(uint4*)&sBl[br][bc]      = *(const uint4*)&g_w2l[(k0 + br) * N + bc];
        *(uint4*)&sBl[br + 16][bc] = *(const uint4*)&g_w2l[(k0 + br + 16) * N + bc];
        __syncthreads();
#pragma unroll
        for (int ks = 0; ks < 2; ks++) {
            wmma::fragment<wmma::matrix_a, 16, 16, 16, __nv_bfloat16, wmma::row_major> fAh[2], fAl[2];
            wmma::fragment<wmma::matrix_b, 16, 16, 16, __nv_bfloat16, wmma::row_major> fBh[2], fBl[2];
#pragma unroll
            for (int i = 0; i < 2; i++) {
                wmma::load_matrix_sync(fAh[i], &sAh[wm + i * 16][ks * 16], 40);
                wmma::load_matrix_sync(fAl[i], &sAl[wm + i * 16][ks * 16], 40);
            }
#pragma unroll
            for (int j = 0; j < 2; j++) {
                wmma::load_matrix_sync(fBh[j], &sBh[ks * 16][wn + j * 16], 136);
                wmma::load_matrix_sync(fBl[j], &sBl[ks * 16][wn + j * 16], 136);
            }
#pragma unroll
            for (int i = 0; i < 2; i++)
#pragma unroll
                for (int j = 0; j < 2; j++) {
                    wmma::mma_sync(acc[i][j], fAh[i], fBh[j], acc[i][j]);
                    wmma::mma_sync(acc[i][j], fAh[i], fBl[j], acc[i][j]);
                    wmma::mma_sync(acc[i][j], fAl[i], fBh[j], acc[i][j]);
                }
        }
        __syncthreads();
    }
#pragma unroll
    for (int i = 0; i < 2; i++)
#pragma unroll
        for (int j = 0; j < 2; j++)
            wmma::store_matrix_sync(&C[(bm + wm + i * 16) * N + wn + j * 16], acc[i][j],
                                    N, wmma::mem_row_major);
}

// ---------------- conv2 agg: warp per node (1 head), fp32 path ----------------
__global__ void k_agg1(const float* __restrict__ xp, const float* __restrict__ als,
                       const float* __restrict__ ald, const float* __restrict__ bias,
                       float* __restrict__ out) {
    int d = (blockIdx.x * blockDim.x + threadIdx.x) >> 5;
    int lane = threadIdx.x & 31;
    if (d >= NN) return;
    int r0 = g_rowptr[d], r1 = g_rowptr[d + 1];
    float aldd = ald[d];
    float alsd = als[d];
    float self_s = lrelu02(alsd + aldd);

    float m = self_s;
    for (int e = r0 + lane; e < r1; e += 32) {
        int s = g_sorted[e];
        m = fmaxf(m, lrelu02(als[s] + aldd));
    }
    m = warp_max(m);

    float w = __expf(self_s - m);
    float denom = w;
    const float* rowp = xp + d * 128;
    float4 xv = *(const float4*)(rowp + lane * 4);
    float4 acc;
    acc.x = w * xv.x; acc.y = w * xv.y; acc.z = w * xv.z; acc.w = w * xv.w;
    for (int e = r0; e < r1; e++) {
        int s = g_sorted[e];   // warp-uniform
        w = __expf(lrelu02(als[s] + aldd) - m);
        denom += w;
        const float* rp = xp + s * 128;
        float4 v = *(const float4*)(rp + lane * 4);
        acc.x += w * v.x; acc.y += w * v.y; acc.z += w * v.z; acc.w += w * v.w;
    }
    float inv = 1.f / denom;
    float4 bv = *(const float4*)(bias + lane * 4);
    float4 o;
    o.x = elu1(acc.x * inv + bv.x);
    o.y = elu1(acc.y * inv + bv.y);
    o.z = elu1(acc.z * inv + bv.z);
    o.w = elu1(acc.w * inv + bv.w);
    *(float4*)(out + d * 128 + lane * 4) = o;
}

// ---------------- masked mean pooling ----------------
__global__ void k_pool(const int* __restrict__ m_idx) {
    int g = blockIdx.x, j = threadIdx.x;   // 128 threads
    float s = 0.f;
    int cnt = 0;
    for (int n = 0; n < MAXNODE; n++) {
        int node = g * MAXNODE + n;
        if (m_idx[node] >= 1) { s += g_x2[node * 128 + j]; cnt++; }
    }
    g_pooled[g * 128 + j] = s / (float)cnt;
}

// ---------------- output head ----------------
__global__ void k_head(const float* __restrict__ Wo1, const float* __restrict__ bo1,
                       const float* __restrict__ Wo2, const float* __restrict__ bo2,
                       float* __restrict__ out) {
    int g = blockIdx.x, j = threadIdx.x;   // 128 threads
    __shared__ float sp[128];
    __shared__ float red[128];
    sp[j] = g_pooled[g * 128 + j];
    __syncthreads();
    float acc = 0.f;
    for (int k = 0; k < 128; k++) acc += sp[k] * Wo1[k * 128 + j];
    acc += bo1[j];
    float h1 = acc > 0.f ? acc : 0.01f * acc;
    red[j] = h1 * Wo2[j];
    __syncthreads();
    for (int off = 64; off > 0; off >>= 1) {
        if (j < off) red[j] += red[j + off];
        __syncthreads();
    }
    if (j == 0) out[g] = red[0] + bo2[0];
}

// ---------------- host ----------------
extern "C" void kernel_launch(void* const* d_in, const int* in_sizes, int n_in,
                              void* d_out, int out_size) {
    int it, iv, im, iei, iWt, ibt, iWv, ibv, iemb, iWn, ibn, iWs, ibs, ilg, ilb;
    int iW1, ias1, iad1, ib1, iW2, ias2, iad2, ib2, iWo1, ibo1, iWo2, ibo2;
    if (in_sizes[2] == NN) {   // setup_inputs dict order
        it = 0; iv = 1; im = 2; iei = 3; iWt = 4; ibt = 5; iWv = 6; ibv = 7;
        iemb = 8; iWn = 9; ibn = 10; iWs = 11; ibs = 12; ilg = 13; ilb = 14;
        iW1 = 15; ias1 = 16; iad1 = 17; ib1 = 18; iW2 = 19; ias2 = 20; iad2 = 21;
        ib2 = 22; iWo1 = 23; ibo1 = 24; iWo2 = 25; ibo2 = 26;
    } else {                   // reference() signature order
        it = 0; iv = 1; iWt = 2; ibt = 3; iWv = 4; ibv = 5; iemb = 6; iWn = 7;
        ibn = 8; iWs = 9; ibs = 10; ilg = 11; ilb = 12; iW1 = 13; ias1 = 14;
        iad1 = 15; ib1 = 16; iW2 = 17; ias2 = 18; iad2 = 19; ib2 = 20;
        iWo1 = 21; ibo1 = 22; iWo2 = 23; ibo2 = 24; im = 25; iei = 26;
    }
    const float* t   = (const float*)d_in[it];
    const float* v   = (const float*)d_in[iv];
    const int*   mi  = (const int*)d_in[im];
    const int*   ei  = (const int*)d_in[iei];
    const float* Wt  = (const float*)d_in[iWt];
    const float* bt  = (const float*)d_in[ibt];
    const float* Wv  = (const float*)d_in[iWv];
    const float* bv  = (const float*)d_in[ibv];
    const float* emb = (const float*)d_in[iemb];
    const float* Wn  = (const float*)d_in[iWn];
    const float* bn  = (const float*)d_in[ibn];
    const float* Ws  = (const float*)d_in[iWs];
    const float* bs  = (const float*)d_in[ibs];
    const float* lg  = (const float*)d_in[ilg];
    const float* lb  = (const float*)d_in[ilb];
    const float* W1  = (const float*)d_in[iW1];
    const float* as1 = (const float*)d_in[ias1];
    const float* ad1 = (const float*)d_in[iad1];
    const float* b1  = (const float*)d_in[ib1];
    const float* W2  = (const float*)d_in[iW2];
    const float* as2 = (const float*)d_in[ias2];
    const float* ad2 = (const float*)d_in[iad2];
    const float* b2  = (const float*)d_in[ib2];
    const float* Wo1 = (const float*)d_in[iWo1];
    const float* bo1 = (const float*)d_in[ibo1];
    const float* Wo2 = (const float*)d_in[iWo2];
    const float* bo2 = (const float*)d_in[ibo2];
    const int* esrc = ei;
    const int* edst = ei + EE;

    float *p_x0t, *p_xp1t, *p_als1, *p_ald1, *p_xp2, *p_x2, *p_als2, *p_ald2;
    cudaGetSymbolAddress((void**)&p_x0t, g_x0t);
    cudaGetSymbolAddress((void**)&p_xp1t, g_xp1t);
    cudaGetSymbolAddress((void**)&p_als1, g_als1);
    cudaGetSymbolAddress((void**)&p_ald1, g_ald1);
    cudaGetSymbolAddress((void**)&p_xp2, g_xp2);
    cudaGetSymbolAddress((void**)&p_x2, g_x2);
    cudaGetSymbolAddress((void**)&p_als2, g_als2);
    cudaGetSymbolAddress((void**)&p_ald2, g_ald2);

    // stage 1: embeds + row table + layernorm
    k_tv<<<GG / 4, 256>>>(t, v, Wt, bt, Wv, bv);
    k_start<<<GG / 4, 128>>>(Ws, bs);
    k_embproj<<<51, 128>>>(emb, Wn, bn);
    k_buildtab<<<(NROWP * 32 + 255) / 256, 256>>>(lg, lb);
    k_rid<<<NN / 256, 256>>>(mi);
    k_w2split<<<(512 * 128) / 256, 256>>>(W2);

    // edge CSR (independent of features)
    k_zero<<<NN / 256, 256>>>();
    k_hist<<<EE / 256, 256>>>(edst);
    k_scan<<<1, 1024>>>();
    k_scatter<<<EE / 256, 256>>>(esrc, edst);

    // conv1 on the 563-row table: xp1t = x0t @ W1 (M=576, K=128, N=512)
    k_gemm<<<dim3(8, NROWP / 64), 256>>>(p_x0t, W1, p_xp1t, 512, 128);
    k_attn<4><<<(NROW * 4 * 32 + 255) / 256, 256>>>(p_xp1t, as1, ad1, p_als1, p_ald1, NROW);
    k_agg4bf<<<(NN * 4 * 32) / 256, 256>>>(p_xp1t, p_als1, p_ald1, b1);

    // conv2: xp2 = x1 @ W2 via split-bf16 tensor cores (M=NN, K=512, N=128)
    k_wmma<<<NN / 64, 256>>>(p_xp2);
    k_attn<1><<<(NN * 32) / 256, 256>>>(p_xp2, as2, ad2, p_als2, p_ald2, NN);
    k_agg1<<<(NN * 32) / 256, 256>>>(p_xp2, p_als2, p_ald2, b2, p_x2);

    // pool + head
    k_pool<<<GG, 128>>>(mi);
    k_head<<<GG, 128>>>(Wo1, bo1, Wo2, bo2, (float*)d_out);
}